// round 9
// baseline (speedup 1.0000x reference)
#include <cuda_runtime.h>
#include <cstdint>

// Inverse 2D Haar wavelet (synthesis), fixed shapes:
//   in : (B=32, C4=256, H=64, W=64) f32   (C4 = C*4: cA,cH,cV,cD per channel)
//   out: (B=32, C=64, 128, 128) f32
//
// Thread = 4 input cols of one row:
//   loads : 4x LDG.128 (__ldcg, L2-only — input is single-use) per subband,
//           each warp-load covers 2 rows x 256B contiguous
//   stores: 2x STG.256 (v8.b32), 32B/lane, 512B contiguous per row-half
// No L2 policy descriptors (persisting carveout is 0 and can't be raised
// under harness rules — policies proven no-ops in R4/R6/R7).

#define IWT_H 64
#define IWT_W 64
#define PLANE_IN  (IWT_H * IWT_W)          // 4096
#define PLANE_OUT (4 * IWT_H * IWT_W)      // 16384

__device__ __forceinline__ void stg8(float* p, const float* r) {
    asm volatile("st.global.v8.b32 [%0], {%1,%2,%3,%4,%5,%6,%7,%8};"
                 :: "l"(p),
                    "r"(__float_as_uint(r[0])), "r"(__float_as_uint(r[1])),
                    "r"(__float_as_uint(r[2])), "r"(__float_as_uint(r[3])),
                    "r"(__float_as_uint(r[4])), "r"(__float_as_uint(r[5])),
                    "r"(__float_as_uint(r[6])), "r"(__float_as_uint(r[7]))
                 : "memory");
}

__global__ void __launch_bounds__(512) iwt_kernel(
    const float* __restrict__ x, float* __restrict__ out)
{
    int t = blockIdx.x * blockDim.x + threadIdx.x;
    int i  = t & 15;           // 16 threads per row, 4 cols each
    int h  = (t >> 4) & 63;
    int bc = t >> 10;          // 0 .. 2047

    const float4* base = (const float4*)(x + (size_t)bc * 4 * PLANE_IN + h * IWT_W + 4 * i);
    float4 a  = __ldcg(base);
    float4 hh = __ldcg(base + PLANE_IN / 4);
    float4 v  = __ldcg(base + 2 * PLANE_IN / 4);
    float4 d  = __ldcg(base + 3 * PLANE_IN / 4);

    float r0[8], r1[8];
    {
        float ai = a.x, hi = hh.x, vi = v.x, di = d.x;
        r0[0] = (ai + hi + vi + di) * 0.5f;
        r0[1] = (ai + hi - vi - di) * 0.5f;
        r1[0] = (ai - hi + vi - di) * 0.5f;
        r1[1] = (ai - hi - vi + di) * 0.5f;
    }
    {
        float ai = a.y, hi = hh.y, vi = v.y, di = d.y;
        r0[2] = (ai + hi + vi + di) * 0.5f;
        r0[3] = (ai + hi - vi - di) * 0.5f;
        r1[2] = (ai - hi + vi - di) * 0.5f;
        r1[3] = (ai - hi - vi + di) * 0.5f;
    }
    {
        float ai = a.z, hi = hh.z, vi = v.z, di = d.z;
        r0[4] = (ai + hi + vi + di) * 0.5f;
        r0[5] = (ai + hi - vi - di) * 0.5f;
        r1[4] = (ai - hi + vi - di) * 0.5f;
        r1[5] = (ai - hi - vi + di) * 0.5f;
    }
    {
        float ai = a.w, hi = hh.w, vi = v.w, di = d.w;
        r0[6] = (ai + hi + vi + di) * 0.5f;
        r0[7] = (ai + hi - vi - di) * 0.5f;
        r1[6] = (ai - hi + vi - di) * 0.5f;
        r1[7] = (ai - hi - vi + di) * 0.5f;
    }

    float* o = out + (size_t)bc * PLANE_OUT + (2 * h) * (2 * IWT_W) + 8 * i;
    stg8(o,             r0);   // row 2h
    stg8(o + 2 * IWT_W, r1);   // row 2h+1
}

extern "C" void kernel_launch(void* const* d_in, const int* in_sizes, int n_in,
                              void* d_out, int out_size) {
    const float* x = (const float*)d_in[0];
    float* out = (float*)d_out;

    int total = in_sizes[0];            // 33,554,432 elems
    int threads_total = total / 16;     // 16 input elems per thread

    int threads = 512;
    int blocks = threads_total / threads;   // 4096
    iwt_kernel<<<blocks, threads>>>(x, out);
}

// round 10
// speedup vs baseline: 1.0072x; 1.0072x over previous
#include <cuda_runtime.h>
#include <cstdint>

// Inverse 2D Haar wavelet (synthesis), fixed shapes:
//   in : (B=32, C4=256, H=64, W=64) f32   (C4 = C*4: cA,cH,cV,cD per channel)
//   out: (B=32, C=64, 128, 128) f32
//
// Warp-per-input-row mapping (best known, R8):
//   lane i loads input cols [2i,2i+2) per subband (float2, 256B/warp/subband)
//   lane i stores output cols [4i,4i+4) of rows 2h, 2h+1 (float4, 512B/warp/STG)
//
// loads : __ldcg  (L2-only; input is single-use, skip L1 fill)
// stores: __stcs  (legacy streaming cache-op; unlike evict_last policy this
//         needs no persisting carveout — demotes write-allocated lines so
//         they stop churning read lines out of L2 between graph replays)

#define IWT_H 64
#define IWT_W 64
#define PLANE_IN  (IWT_H * IWT_W)          // 4096
#define PLANE_OUT (4 * IWT_H * IWT_W)      // 16384

__global__ void __launch_bounds__(512) iwt_kernel(
    const float* __restrict__ x, float* __restrict__ out)
{
    int t = blockIdx.x * blockDim.x + threadIdx.x;
    int lane = t & 31;
    int w = t >> 5;          // warp index = (bc, h)
    int h = w & 63;
    int bc = w >> 6;         // 0 .. B*C-1 (2048)

    const float2* base = (const float2*)(x + (size_t)bc * 4 * PLANE_IN + h * IWT_W + 2 * lane);
    float2 a  = __ldcg(base);
    float2 hh = __ldcg(base + PLANE_IN / 2);
    float2 v  = __ldcg(base + 2 * PLANE_IN / 2);
    float2 d  = __ldcg(base + 3 * PLANE_IN / 2);

    float4 r0, r1;
    {
        float ai = a.x, hi = hh.x, vi = v.x, di = d.x;
        r0.x = (ai + hi + vi + di) * 0.5f;
        r0.y = (ai + hi - vi - di) * 0.5f;
        r1.x = (ai - hi + vi - di) * 0.5f;
        r1.y = (ai - hi - vi + di) * 0.5f;
    }
    {
        float ai = a.y, hi = hh.y, vi = v.y, di = d.y;
        r0.z = (ai + hi + vi + di) * 0.5f;
        r0.w = (ai + hi - vi - di) * 0.5f;
        r1.z = (ai - hi + vi - di) * 0.5f;
        r1.w = (ai - hi - vi + di) * 0.5f;
    }

    float* o = out + (size_t)bc * PLANE_OUT + (2 * h) * (2 * IWT_W) + 4 * lane;
    __stcs((float4*)(o),             r0);   // row 2h
    __stcs((float4*)(o + 2 * IWT_W), r1);   // row 2h+1
}

extern "C" void kernel_launch(void* const* d_in, const int* in_sizes, int n_in,
                              void* d_out, int out_size) {
    const float* x = (const float*)d_in[0];
    float* out = (float*)d_out;

    int total = in_sizes[0];            // 33,554,432 elems
    int threads_total = total / 8;      // 8 elems per thread

    int threads = 512;
    int blocks = threads_total / threads;   // 8192
    iwt_kernel<<<blocks, threads>>>(x, out);
}

// round 11
// speedup vs baseline: 1.0346x; 1.0272x over previous
#include <cuda_runtime.h>
#include <cstdint>

// Inverse 2D Haar wavelet (synthesis), fixed shapes:
//   in : (B=32, C4=256, H=64, W=64) f32   (C4 = C*4: cA,cH,cV,cD per channel)
//   out: (B=32, C=64, 128, 128) f32
//
// FINAL (best measured: kernel 35.42us, DRAM 76.1%, bench 43.49us):
// Warp-per-input-row mapping:
//   lane i loads input cols [2i,2i+2) per subband (float2, 256B/warp/subband,
//     front-batched -> MLP 4)
//   lane i stores output cols [4i,4i+4) of rows 2h and 2h+1 (float4 each,
//     512B fully contiguous per STG.128 -> full-sector store wavefronts)
//   loads via __ldcg: input is single-use, skip the L1 fill.
//
// Measured floor rationale: 268MB/pass compulsory traffic, fixed-order graph
// replay gives a capacity-bound ~22% L2 residue (persisting carveout is
// forbidden by harness rules), and ~74-76% of DRAM spec is the mixed R/W
// stream ceiling. L2 policies (evict_last/evict_first/.cs), larger tiles,
// wider vectors, and wave-count reduction all measured neutral (R3-R10).

#define IWT_H 64
#define IWT_W 64
#define PLANE_IN  (IWT_H * IWT_W)          // 4096
#define PLANE_OUT (4 * IWT_H * IWT_W)      // 16384

__global__ void __launch_bounds__(512) iwt_kernel(
    const float* __restrict__ x, float* __restrict__ out)
{
    int t = blockIdx.x * blockDim.x + threadIdx.x;
    int lane = t & 31;
    int w = t >> 5;          // warp index = (bc, h)
    int h = w & 63;
    int bc = w >> 6;         // 0 .. B*C-1 (2048)

    const float2* base = (const float2*)(x + (size_t)bc * 4 * PLANE_IN + h * IWT_W + 2 * lane);
    float2 a  = __ldcg(base);
    float2 hh = __ldcg(base + PLANE_IN / 2);
    float2 v  = __ldcg(base + 2 * PLANE_IN / 2);
    float2 d  = __ldcg(base + 3 * PLANE_IN / 2);

    float4 r0, r1;
    {
        float ai = a.x, hi = hh.x, vi = v.x, di = d.x;
        r0.x = (ai + hi + vi + di) * 0.5f;
        r0.y = (ai + hi - vi - di) * 0.5f;
        r1.x = (ai - hi + vi - di) * 0.5f;
        r1.y = (ai - hi - vi + di) * 0.5f;
    }
    {
        float ai = a.y, hi = hh.y, vi = v.y, di = d.y;
        r0.z = (ai + hi + vi + di) * 0.5f;
        r0.w = (ai + hi - vi - di) * 0.5f;
        r1.z = (ai - hi + vi - di) * 0.5f;
        r1.w = (ai - hi - vi + di) * 0.5f;
    }

    float* o = out + (size_t)bc * PLANE_OUT + (2 * h) * (2 * IWT_W) + 4 * lane;
    *(float4*)(o)              = r0;   // row 2h
    *(float4*)(o + 2 * IWT_W)  = r1;   // row 2h+1
}

extern "C" void kernel_launch(void* const* d_in, const int* in_sizes, int n_in,
                              void* d_out, int out_size) {
    const float* x = (const float*)d_in[0];
    float* out = (float*)d_out;

    int total = in_sizes[0];            // 33,554,432 elems
    int threads_total = total / 8;      // 8 elems per thread

    int threads = 512;
    int blocks = threads_total / threads;   // 8192
    iwt_kernel<<<blocks, threads>>>(x, out);
}